// round 15
// baseline (speedup 1.0000x reference)
#include <cuda_runtime.h>
#include <math.h>
#include <stdint.h>

// Problem constants (fixed: N=100000, P=256, K=64, R=16)
#define PDIM   256
#define RNK    16
#define KCOMP  64
#define BM     128            // rows per CTA
#define NCHUNK 8              // 8 chunks x 128 cols = 1024 = K*R
#define NPANEL 4              // K split: 4 panels x 64
#define NITER  (NCHUNK * NPANEL)

// dynamic smem map (bytes)
#define SM_AH    0u           // A hi-plane int8: [128 rows][256 B], swizzled 16B chunks
#define SM_AL    32768u       // A lo-plane
#define SM_B     65536u       // 2 stages x (H 8KB + L 8KB) = 32KB
#define SM_TOTAL 98304u

// ------------- scratch (no allocations allowed) -------------
// W blocks [chunk][panel]: 16KB = H[col 128][64B] + L, ldmatrix-swizzled int8.
__device__ __align__(128) unsigned char g_Wb[NITER * 16384];
__device__ float g_cK[KCOMP];
__device__ float g_partials[1024];

// ------------- PTX helpers (plain sm_90-level PTX only) ----
__device__ __forceinline__ uint32_t smem_u32(const void *p) {
    uint32_t a;
    asm("{ .reg .u64 t; cvta.to.shared.u64 t, %1; cvt.u32.u64 %0, t; }"
        : "=r"(a) : "l"(p));
    return a;
}
__device__ __forceinline__ void mbar_init(uint32_t mbar, uint32_t cnt) {
    asm volatile("mbarrier.init.shared.b64 [%0], %1;" :: "r"(mbar), "r"(cnt) : "memory");
}
__device__ __forceinline__ void mbar_expect_tx(uint32_t mbar, uint32_t bytes) {
    asm volatile("mbarrier.arrive.expect_tx.shared.b64 _, [%0], %1;"
                 :: "r"(mbar), "r"(bytes) : "memory");
}
__device__ __forceinline__ void mbar_wait(uint32_t mbar, uint32_t parity) {
    asm volatile(
        "{\n\t.reg .pred P1;\n\t"
        "WL%=:\n\t"
        "mbarrier.try_wait.parity.acquire.cta.shared::cta.b64 P1, [%0], %1, 0x989680;\n\t"
        "@P1 bra.uni WD%=;\n\t"
        "bra.uni WL%=;\n\t"
        "WD%=:\n\t}"
        :: "r"(mbar), "r"(parity) : "memory");
}
__device__ __forceinline__ void bulk_g2s(uint32_t dst, const void *src,
                                         uint32_t bytes, uint32_t mbar) {
    asm volatile(
        "cp.async.bulk.shared::cluster.global.mbarrier::complete_tx::bytes "
        "[%0], [%1], %2, [%3];"
        :: "r"(dst), "l"(src), "r"(bytes), "r"(mbar) : "memory");
}
__device__ __forceinline__ void ldsm4(uint32_t *r, uint32_t addr) {
    asm volatile("ldmatrix.sync.aligned.m8n8.x4.shared.b16 {%0,%1,%2,%3}, [%4];"
                 : "=r"(r[0]), "=r"(r[1]), "=r"(r[2]), "=r"(r[3]) : "r"(addr));
}
// int8 m16n8k32: D += A(16x32 s8) * B(32x8 s8), s32 accum (exact)
__device__ __forceinline__ void mma_s8(int *c, const uint32_t *a,
                                       uint32_t b0, uint32_t b1) {
    asm volatile(
        "mma.sync.aligned.m16n8k32.row.col.s32.s8.s8.s32 "
        "{%0,%1,%2,%3}, {%4,%5,%6,%7}, {%8,%9}, {%0,%1,%2,%3};"
        : "+r"(c[0]), "+r"(c[1]), "+r"(c[2]), "+r"(c[3])
        : "r"(a[0]), "r"(a[1]), "r"(a[2]), "r"(a[3]), "r"(b0), "r"(b1));
}

// ---------------------------------------------------------------------------
// prep: D = I + M^T M; warp-parallel register Cholesky; W = M L^{-T};
// constants; W written as int8 H/L planes into ldmatrix-swizzled gmem blocks.
// ---------------------------------------------------------------------------
__global__ void prep_kernel(const float *__restrict__ M,
                            const float *__restrict__ pi, int K) {
    const int k = blockIdx.x;
    const int t = threadIdx.x;
    __shared__ float Ms[PDIM * RNK];
    __shared__ float Dm[RNK * RNK];
    __shared__ float Lm[RNK * RNK];
    __shared__ float sLogdet;

    for (int i = t; i < PDIM * RNK; i += 256)
        Ms[i] = M[(size_t)k * PDIM * RNK + i];
    __syncthreads();

    {   // G(i,j) with 4-way ILP to break the LDS->FMA chain
        const int i = t >> 4, j = t & 15;
        float s0 = 0.f, s1 = 0.f, s2 = 0.f, s3 = 0.f;
        for (int p = 0; p < PDIM; p += 4) {
            s0 += Ms[(p + 0) * RNK + i] * Ms[(p + 0) * RNK + j];
            s1 += Ms[(p + 1) * RNK + i] * Ms[(p + 1) * RNK + j];
            s2 += Ms[(p + 2) * RNK + i] * Ms[(p + 2) * RNK + j];
            s3 += Ms[(p + 3) * RNK + i] * Ms[(p + 3) * RNK + j];
        }
        Dm[i * RNK + j] = (s0 + s1) + (s2 + s3) + (i == j ? 1.0f : 0.0f);
    }
    __syncthreads();

    // warp 0: register-resident Cholesky, lane i owns row i
    if (t < 32) {
        const unsigned full = 0xffffffffu;
        float row[RNK], Lrow[RNK];
#pragma unroll
        for (int q = 0; q < RNK; q++)
            row[q] = (t < RNK) ? Dm[t * RNK + q] : 0.f;
#pragma unroll
        for (int j = 0; j < RNK; j++) {
            const float dj = __shfl_sync(full, row[j], j);
            const float lj = sqrtf(dj);
            const float lij = (t == j) ? lj : row[j] * (1.0f / lj);
            Lrow[j] = lij;
#pragma unroll
            for (int mm = 0; mm < RNK; mm++) {
                if (mm > j) {
                    const float lmj = __shfl_sync(full, lij, mm);
                    row[mm] -= lij * lmj;
                }
            }
        }
        if (t < RNK) {
#pragma unroll
            for (int j = 0; j < RNK; j++) Lm[t * RNK + j] = Lrow[j];
        }
        float v = (t < RNK) ? logf(Lrow[t]) : 0.f;
#pragma unroll
        for (int off = 16; off > 0; off >>= 1)
            v += __shfl_down_sync(full, v, off);
        if (t == 0) sLogdet = 2.0f * v;
    }
    __syncthreads();

    if (t == 0) {
        float mx = -1e30f;
        for (int q = 0; q < K; q++) mx = fmaxf(mx, pi[q]);
        float ss = 0.f;
        for (int q = 0; q < K; q++) ss += expf(pi[q] - mx);
        float lse = mx + logf(ss);
        double half_p = 0.5 * (double)PDIM;
        double logSA = lgamma(half_p) - log(2.0) - half_p * log(3.14159265358979323846);
        g_cK[k] = (float)logSA - 0.5f * sLogdet + (pi[k] - lse);
    }

    // Row p: solve w L^T = m, write int8 H/L into swizzled block layout.
    {
        const int p = t;        // global k-index 0..255
        float w[RNK];
#pragma unroll
        for (int j = 0; j < RNK; j++) {
            float v = Ms[p * RNK + j];
#pragma unroll
            for (int i = 0; i < RNK; i++)
                if (i < j) v -= Lm[j * RNK + i] * w[i];
            w[j] = v / Lm[j * RNK + j];
        }
        const int chunk = k >> 3;       // 8 comps per 128-col chunk
        const int panel = p >> 6;       // K panel (64 each)
        const int kk    = p & 63;
        const int ckn   = kk >> 4;      // 16B chunk within 64B col-row (0..3)
        const int byt   = kk & 15;
#pragma unroll
        for (int j = 0; j < RNK; j++) {
            int col = (k & 7) * RNK + j;              // 0..127 within chunk
            uint32_t off = (uint32_t)(chunk * NPANEL + panel) * 16384u
                         + (uint32_t)col * 64u
                         + (uint32_t)((ckn ^ ((col >> 1) & 3)) * 16 + byt);
            float ws = w[j] * 126.f;
            float hr = rintf(ws);
            hr = fminf(127.f, fmaxf(-127.f, hr));
            float lr = rintf((ws - hr) * 254.f);
            lr = fminf(127.f, fmaxf(-127.f, lr));
            g_Wb[off]          = (unsigned char)(signed char)(int)hr;
            g_Wb[off + 8192u]  = (unsigned char)(signed char)(int)lr;
        }
    }
}

// ---------------------------------------------------------------------------
// Fused GEMM (mma.sync int8 k32, exact 2-level fixed point, 3 MMA terms)
// + density + online LSE. 8 warps: wr = wid&3 (32-row band), wn = wid>>2
// (64-col half). acc1 = Sum Hx*Hw, acc2 = Sum (Hx*Lw + Lx*Hw), both s32 exact.
// y = (acc1 + acc2/254) / (126*126).
// ---------------------------------------------------------------------------
__global__ __launch_bounds__(256) void gemm_kernel(const float *__restrict__ X,
                                                   int N) {
    extern __shared__ unsigned char smc[];
    const uint32_t sb = smem_u32(smc);
    const int t = threadIdx.x;
    const int wid = t >> 5;
    const int lane = t & 31;
    const int wr = wid & 3;
    const int wn = wid >> 2;
    const int tid4 = lane & 3;
    const int group = lane >> 2;
    const int row0 = blockIdx.x * BM;

    __shared__ float cKs[KCOMP];
    __shared__ uint64_t barsS[2];
    __shared__ float mergeM[4][32], mergeS[4][32];
    __shared__ float wsumS[4];
    const uint32_t bar0 = smem_u32(&barsS[0]);
    const uint32_t bar1 = smem_u32(&barsS[1]);

    if (t == 0) {
        mbar_init(bar0, 1);
        mbar_init(bar1, 1);
        asm volatile("fence.proxy.async.shared::cta;" ::: "memory");
        mbar_expect_tx(bar0, 16384);
        bulk_g2s(sb + SM_B, g_Wb, 16384, bar0);
        mbar_expect_tx(bar1, 16384);
        bulk_g2s(sb + SM_B + 16384u, g_Wb + 16384, 16384, bar1);
    }
    if (t < KCOMP) cKs[t] = g_cK[t];

    // ---- stage A: X fp32 -> int8 H/L planes, swizzled 16B chunks ----
    for (int i = t; i < BM * 32; i += 256) {
        const int row = i >> 5;
        const int c8  = i & 31;               // 8-float chunk along k
        float4 v0 = make_float4(0.f, 0.f, 0.f, 0.f), v1 = v0;
        if (row0 + row < N) {
            const float *src = &X[(size_t)(row0 + row) * PDIM + c8 * 8];
            v0 = *reinterpret_cast<const float4 *>(src);
            v1 = *reinterpret_cast<const float4 *>(src + 4);
        }
        float f[8] = {v0.x, v0.y, v0.z, v0.w, v1.x, v1.y, v1.z, v1.w};
        int hb[8], lb[8];
#pragma unroll
        for (int j = 0; j < 8; j++) {
            float xs = f[j] * 126.f;          // |x| <= 1 exactly (unit-norm rows)
            float hr = rintf(xs);
            float lr = rintf((xs - hr) * 254.f);
            hb[j] = (int)hr;
            lb[j] = (int)lr;
        }
        uint32_t hw0 = (uint32_t)(hb[0] & 255) | ((uint32_t)(hb[1] & 255) << 8)
                     | ((uint32_t)(hb[2] & 255) << 16) | ((uint32_t)(hb[3] & 255) << 24);
        uint32_t hw1 = (uint32_t)(hb[4] & 255) | ((uint32_t)(hb[5] & 255) << 8)
                     | ((uint32_t)(hb[6] & 255) << 16) | ((uint32_t)(hb[7] & 255) << 24);
        uint32_t lw0 = (uint32_t)(lb[0] & 255) | ((uint32_t)(lb[1] & 255) << 8)
                     | ((uint32_t)(lb[2] & 255) << 16) | ((uint32_t)(lb[3] & 255) << 24);
        uint32_t lw1 = (uint32_t)(lb[4] & 255) | ((uint32_t)(lb[5] & 255) << 8)
                     | ((uint32_t)(lb[6] & 255) << 16) | ((uint32_t)(lb[7] & 255) << 24);
        const int ckI = c8 >> 1;              // 16B chunk 0..15
        const uint32_t sub = (uint32_t)(c8 & 1) * 8u;
        const uint32_t addr = (uint32_t)row * 256u
            + (uint32_t)((ckI & ~7) | ((ckI & 7) ^ (row & 7))) * 16u + sub;
        asm volatile("st.shared.v2.b32 [%0], {%1,%2};"
                     :: "r"(sb + SM_AH + addr), "r"(hw0), "r"(hw1));
        asm volatile("st.shared.v2.b32 [%0], {%1,%2};"
                     :: "r"(sb + SM_AL + addr), "r"(lw0), "r"(lw1));
    }
    __syncthreads();

    float lm = -1e30f, ls = 0.f;         // per-lane online logsumexp
    int ph0 = 0, ph1 = 0;
    int acc1[2][8][4], acc2[2][8][4];
    const float INV254 = 1.0f / 254.0f;
    const float INV_SS = 1.0f / (126.0f * 126.0f);

    for (int chunk = 0; chunk < NCHUNK; chunk++) {
#pragma unroll
        for (int m2 = 0; m2 < 2; m2++)
#pragma unroll
            for (int nt = 0; nt < 8; nt++)
#pragma unroll
                for (int j = 0; j < 4; j++) { acc1[m2][nt][j] = 0; acc2[m2][nt][j] = 0; }

        for (int panel = 0; panel < NPANEL; panel++) {
            const int iter = chunk * NPANEL + panel;
            const int stg = iter & 1;
            if (stg == 0) { mbar_wait(bar0, (uint32_t)ph0); ph0 ^= 1; }
            else          { mbar_wait(bar1, (uint32_t)ph1); ph1 ^= 1; }

            const uint32_t bB = sb + SM_B + (uint32_t)stg * 16384u;
#pragma unroll
            for (int ks2 = 0; ks2 < 2; ks2++) {
                const int s2 = panel * 2 + ks2;         // global k32 step 0..7
                const int lm8 = lane >> 3;
                uint32_t ah[2][4], al[2][4];
#pragma unroll
                for (int m2 = 0; m2 < 2; m2++) {
                    const int rowl = wr * 32 + m2 * 16 + ((lm8 & 1) << 3) + (lane & 7);
                    const int ckA = s2 * 2 + (lm8 >> 1);
                    const uint32_t ad = sb + SM_AH + (uint32_t)rowl * 256u
                        + (uint32_t)((ckA & ~7) | ((ckA & 7) ^ (rowl & 7))) * 16u;
                    ldsm4(ah[m2], ad);
                    ldsm4(al[m2], ad + 32768u);
                }
#pragma unroll
                for (int ng = 0; ng < 4; ng++) {
                    const int colb = wn * 64 + ng * 16 + ((lm8 & 2) << 2) + (lane & 7);
                    const int ckB = ks2 * 2 + (lm8 & 1);
                    const uint32_t bd = bB + (uint32_t)colb * 64u
                        + (uint32_t)((ckB ^ ((colb >> 1) & 3)) * 16);
                    uint32_t bh[4], bl[4];
                    ldsm4(bh, bd);
                    ldsm4(bl, bd + 8192u);
#pragma unroll
                    for (int m2 = 0; m2 < 2; m2++)
#pragma unroll
                        for (int tt = 0; tt < 2; tt++) {
                            const int nt = ng * 2 + tt;
                            mma_s8(acc1[m2][nt], ah[m2], bh[2 * tt], bh[2 * tt + 1]);
                            mma_s8(acc2[m2][nt], ah[m2], bl[2 * tt], bl[2 * tt + 1]);
                            mma_s8(acc2[m2][nt], al[m2], bh[2 * tt], bh[2 * tt + 1]);
                        }
                }
            }
            __syncthreads();
            if (t == 0 && iter + 2 < NITER) {
                const uint32_t bar = stg ? bar1 : bar0;
                mbar_expect_tx(bar, 16384);
                bulk_g2s(sb + SM_B + (uint32_t)stg * 16384u,
                         g_Wb + (size_t)(iter + 2) * 16384u, 16384, bar);
            }
        }

        // ---- chunk epilogue: scale -> y -> quad -> density -> online LSE ----
#pragma unroll
        for (int c2 = 0; c2 < 4; c2++) {
            float qsel = 0.f;
#pragma unroll
            for (int m2 = 0; m2 < 2; m2++)
#pragma unroll
                for (int h = 0; h < 2; h++) {
                    float q = 0.f;
#pragma unroll
                    for (int dn = 0; dn < 2; dn++) {
                        const int nt = 2 * c2 + dn;
#pragma unroll
                        for (int j = 0; j < 2; j++) {
                            const int ci = 2 * h + j;
                            float y = ((float)acc1[m2][nt][ci]
                                       + (float)acc2[m2][nt][ci] * INV254) * INV_SS;
                            q += y * y;
                        }
                    }
                    q += __shfl_xor_sync(0xffffffffu, q, 1);
                    q += __shfl_xor_sync(0xffffffffu, q, 2);
                    if (tid4 == m2 * 2 + h) qsel = q;
                }
            const int comp = chunk * 8 + wn * 4 + c2;
            const float dens = cKs[comp] - 128.0f * log1pf(-qsel);
            const float nm = fmaxf(lm, dens);
            ls = ls * expf(lm - nm) + expf(dens - nm);
            lm = nm;
        }
    }

    // ---- merge the two wn halves, per-row value, deterministic block sum ----
    if (wn == 1) { mergeM[wr][lane] = lm; mergeS[wr][lane] = ls; }
    __syncthreads();
    if (wn == 0) {
        const float m2v = mergeM[wr][lane], s2v = mergeS[wr][lane];
        const float nm = fmaxf(lm, m2v);
        const float s = ls * expf(lm - nm) + s2v * expf(m2v - nm);
        const int rowl = wr * 32 + (tid4 >> 1) * 16 + (tid4 & 1) * 8 + group;
        float rv = (row0 + rowl < N) ? (nm + logf(s)) : 0.f;
#pragma unroll
        for (int off = 16; off > 0; off >>= 1)
            rv += __shfl_down_sync(0xffffffffu, rv, off);
        if (lane == 0) wsumS[wr] = rv;
    }
    __syncthreads();
    if (t == 0)
        g_partials[blockIdx.x] = (wsumS[0] + wsumS[1]) + (wsumS[2] + wsumS[3]);
}

// ---------------------------------------------------------------------------
__global__ void reduce_kernel(int nb, float *__restrict__ out) {
    __shared__ double sd[256];
    double s = 0.0;
    for (int i = threadIdx.x; i < nb; i += 256) s += (double)g_partials[i];
    sd[threadIdx.x] = s;
    __syncthreads();
    for (int off = 128; off > 0; off >>= 1) {
        if (threadIdx.x < off) sd[threadIdx.x] += sd[threadIdx.x + off];
        __syncthreads();
    }
    if (threadIdx.x == 0) out[0] = (float)sd[0];
}

// ---------------------------------------------------------------------------
extern "C" void kernel_launch(void *const *d_in, const int *in_sizes, int n_in,
                              void *d_out, int out_size) {
    const float *X  = (const float *)d_in[0];
    const float *M  = (const float *)d_in[1];
    const float *pi = (const float *)d_in[2];
    const int K = in_sizes[2];
    const int N = in_sizes[0] / PDIM;

    prep_kernel<<<K, 256>>>(M, pi, K);

    const int nb = (N + BM - 1) / BM;
    cudaFuncSetAttribute(gemm_kernel,
                         cudaFuncAttributeMaxDynamicSharedMemorySize,
                         (int)SM_TOTAL);
    gemm_kernel<<<nb, 256, SM_TOTAL>>>(X, N);

    reduce_kernel<<<1, 256>>>(nb, (float *)d_out);
}